// round 1
// baseline (speedup 1.0000x reference)
#include <cuda_runtime.h>
#include <cuda_bf16.h>
#include <math.h>

#define D_HIDDEN 1024
#define D_INTER  4096
#define NE       8
#define NTOK     2048
#define NPAIR    (NTOK * 2)
#define GU_ROWS  (2 * D_INTER)   // 8192

// MXFP4 E2M1 LUT
__constant__ float c_lut[16] = {
    0.0f, 0.5f, 1.0f, 1.5f, 2.0f, 3.0f, 4.0f, 6.0f,
   -0.0f,-0.5f,-1.0f,-1.5f,-2.0f,-3.0f,-4.0f,-6.0f};

// ---- device scratch (no allocations allowed) ----
__device__ int   g_top_idx[NTOK][2];
__device__ float g_top_w[NTOK][2];
__device__ int   g_count[NE];
__device__ int   g_off[NE];
__device__ int   g_list[NE][NTOK];
__device__ float g_coefs[NE][NTOK];
__device__ float g_act[(size_t)NPAIR * D_INTER];   // 64 MB activation scratch

// ============================================================
// Zero output
// ============================================================
__global__ void zero_kernel(float* __restrict__ out, int n) {
    int i = blockIdx.x * blockDim.x + threadIdx.x;
    if (i < n) out[i] = 0.0f;
}

// ============================================================
// Router: one warp per token. logits = x @ Wr^T + b; top2; softmax over 2.
// ============================================================
__global__ void router_kernel(const float* __restrict__ x,
                              const float* __restrict__ rw,
                              const float* __restrict__ rb) {
    int warp = threadIdx.x >> 5;
    int lane = threadIdx.x & 31;
    int t = blockIdx.x * 8 + warp;
    if (t >= NTOK) return;

    float acc[NE];
#pragma unroll
    for (int e = 0; e < NE; e++) acc[e] = 0.0f;

    const float* xr = x + (size_t)t * D_HIDDEN;
    for (int k = lane; k < D_HIDDEN; k += 32) {
        float xv = xr[k];
#pragma unroll
        for (int e = 0; e < NE; e++) acc[e] += xv * rw[e * D_HIDDEN + k];
    }
#pragma unroll
    for (int e = 0; e < NE; e++) {
#pragma unroll
        for (int o = 16; o > 0; o >>= 1)
            acc[e] += __shfl_xor_sync(0xffffffffu, acc[e], o);
    }
    if (lane == 0) {
        float v[NE];
#pragma unroll
        for (int e = 0; e < NE; e++) v[e] = acc[e] + rb[e];
        int i0 = 0;
#pragma unroll
        for (int e = 1; e < NE; e++) if (v[e] > v[i0]) i0 = e;
        int i1 = -1;
#pragma unroll
        for (int e = 0; e < NE; e++) {
            if (e == i0) continue;
            if (i1 < 0 || v[e] > v[i1]) i1 = e;
        }
        float w1 = expf(v[i1] - v[i0]);   // <= 1
        float inv = 1.0f / (1.0f + w1);
        g_top_idx[t][0] = i0; g_top_idx[t][1] = i1;
        g_top_w[t][0] = inv;  g_top_w[t][1] = w1 * inv;
    }
}

// ============================================================
// Deterministic per-expert compaction (one block per expert).
// ============================================================
__global__ void compact_kernel() {
    const int e = blockIdx.x;
    const int tid = threadIdx.x;
    __shared__ int scan[256];
    __shared__ int sbase;
    if (tid == 0) sbase = 0;
    __syncthreads();

    for (int c = 0; c < NTOK; c += 256) {
        int t = c + tid;
        int i0 = g_top_idx[t][0];
        int i1 = g_top_idx[t][1];
        int flag = (i0 == e) || (i1 == e);
        float coef = (i0 == e) ? g_top_w[t][0] : g_top_w[t][1];

        scan[tid] = flag;
        __syncthreads();
#pragma unroll
        for (int off = 1; off < 256; off <<= 1) {
            int v = (tid >= off) ? scan[tid - off] : 0;
            __syncthreads();
            scan[tid] += v;
            __syncthreads();
        }
        if (flag) {
            int pos = sbase + scan[tid] - 1;
            g_list[e][pos]  = t;
            g_coefs[e][pos] = coef;
        }
        __syncthreads();
        if (tid == 0) sbase += scan[255];
        __syncthreads();
    }
    if (tid == 0) g_count[e] = sbase;
}

__global__ void offsets_kernel() {
    if (threadIdx.x == 0) {
        int r = 0;
#pragma unroll
        for (int e = 0; e < NE; e++) { g_off[e] = r; r += g_count[e]; }
    }
}

// ============================================================
// GEMM1: act[pair, 4096] = SwiGLU( x[tok] @ Wgu[e]^T + bias )
// Tiles: BM=128 pairs, BN=128 rows, BK=32 (one MXFP4 scale block).
// 256 threads, 8x8 micro-tile (4+4 split float4 fragments).
// ============================================================
__global__ __launch_bounds__(256) void gemm1_kernel(
    const float* __restrict__ x,
    const int* __restrict__ gub,
    const int* __restrict__ gus,
    const float* __restrict__ gbias) {

    const int mtile = blockIdx.y;
    const int e  = mtile >> 4;
    const int m0 = (mtile & 15) << 7;
    const int cnt = g_count[e];
    if (m0 >= cnt) return;
    const int valid = min(128, cnt - m0);
    const int r0 = blockIdx.x << 7;
    const int off = g_off[e];

    __shared__ float As[32][128];
    __shared__ float Bs[32][128];
    __shared__ int   stok[128];
    __shared__ float slut[16];

    const int tid = threadIdx.x;
    if (tid < 16) slut[tid] = c_lut[tid];
    if (tid < 128) stok[tid] = g_list[e][m0 + ((tid < valid) ? tid : 0)];
    __syncthreads();

    const int tx = tid & 15, ty = tid >> 4;

    // A-fill mapping: thread -> (row m, 16 consecutive k)
    const int am = tid >> 1;
    const int ak = (tid & 1) << 4;
    const float* xrow = x + (size_t)stok[am] * D_HIDDEN + ak;

    // B-fill mapping: thread handles int4 groups g and g+256 (row = g>>2, quarter = g&3)
    const int br0 = tid >> 2,         bq0 = tid & 3;
    const int br1 = (tid + 256) >> 2, bq1 = (tid + 256) & 3;
    const int4* bp0 = (const int4*)gub + ((size_t)(e * GU_ROWS + r0 + br0) * 32) * 4 + bq0;
    const int4* bp1 = (const int4*)gub + ((size_t)(e * GU_ROWS + r0 + br1) * 32) * 4 + bq1;
    const int* sp0 = gus + (size_t)(e * GU_ROWS + r0 + br0) * 32;
    const int* sp1 = gus + (size_t)(e * GU_ROWS + r0 + br1) * 32;

    float acc[8][8];
#pragma unroll
    for (int i = 0; i < 8; i++)
#pragma unroll
        for (int j = 0; j < 8; j++) acc[i][j] = 0.0f;

    for (int kb = 0; kb < D_HIDDEN / 32; ++kb) {
        // ---- A tile ----
        const float4* xp = (const float4*)(xrow + kb * 32);
        float4 a0 = xp[0], a1 = xp[1], a2 = xp[2], a3 = xp[3];
        As[ak + 0][am] = a0.x; As[ak + 1][am] = a0.y; As[ak + 2][am] = a0.z; As[ak + 3][am] = a0.w;
        As[ak + 4][am] = a1.x; As[ak + 5][am] = a1.y; As[ak + 6][am] = a1.z; As[ak + 7][am] = a1.w;
        As[ak + 8][am] = a2.x; As[ak + 9][am] = a2.y; As[ak +10][am] = a2.z; As[ak +11][am] = a2.w;
        As[ak +12][am] = a3.x; As[ak +13][am] = a3.y; As[ak +14][am] = a3.z; As[ak +15][am] = a3.w;
        // ---- B tile (fused dequant) ----
        {
            int4 q = bp0[kb * 4];
            float s = __int_as_float(sp0[kb] << 23);
            int vv[4] = {q.x, q.y, q.z, q.w};
#pragma unroll
            for (int ii = 0; ii < 4; ++ii) {
                int k2 = (bq0 * 4 + ii) * 2;
                Bs[k2][br0]     = slut[vv[ii] & 15] * s;
                Bs[k2 + 1][br0] = slut[(vv[ii] >> 4) & 15] * s;
            }
        }
        {
            int4 q = bp1[kb * 4];
            float s = __int_as_float(sp1[kb] << 23);
            int vv[4] = {q.x, q.y, q.z, q.w};
#pragma unroll
            for (int ii = 0; ii < 4; ++ii) {
                int k2 = (bq1 * 4 + ii) * 2;
                Bs[k2][br1]     = slut[vv[ii] & 15] * s;
                Bs[k2 + 1][br1] = slut[(vv[ii] >> 4) & 15] * s;
            }
        }
        __syncthreads();
#pragma unroll
        for (int k = 0; k < 32; k++) {
            float4 fa0 = *(const float4*)&As[k][ty * 4];
            float4 fa1 = *(const float4*)&As[k][64 + ty * 4];
            float4 fb0 = *(const float4*)&Bs[k][tx * 4];
            float4 fb1 = *(const float4*)&Bs[k][64 + tx * 4];
            float av[8] = {fa0.x, fa0.y, fa0.z, fa0.w, fa1.x, fa1.y, fa1.z, fa1.w};
            float bv[8] = {fb0.x, fb0.y, fb0.z, fb0.w, fb1.x, fb1.y, fb1.z, fb1.w};
#pragma unroll
            for (int i = 0; i < 8; i++)
#pragma unroll
                for (int j = 0; j < 8; j++) acc[i][j] += av[i] * bv[j];
        }
        __syncthreads();
    }

    // ---- Epilogue: bias + SwiGLU, write act ----
#pragma unroll
    for (int i = 0; i < 8; i++) {
        int m = (i < 4) ? (ty * 4 + i) : (64 + ty * 4 + (i - 4));
        if (m >= valid) continue;
        float* arow = g_act + (size_t)(off + m0 + m) * D_INTER;
#pragma unroll
        for (int jp = 0; jp < 4; jp++) {
            int j = jp * 2;
            int c = (jp < 2) ? (r0 + tx * 4 + j) : (r0 + 64 + tx * 4 + (j - 4));
            float gate = acc[i][j]     + gbias[(size_t)e * GU_ROWS + c];
            float up   = acc[i][j + 1] + gbias[(size_t)e * GU_ROWS + c + 1];
            gate = fminf(gate, 7.0f);
            up   = fminf(fmaxf(up, -7.0f), 7.0f);
            float sg = 1.0f / (1.0f + expf(-1.702f * gate));
            arow[c >> 1] = (up + 1.0f) * (gate * sg);
        }
    }
}

// ============================================================
// GEMM2: out[tok] += coef * ( act[pair] @ Wd[e]^T + down_bias )
// K = 4096, N = 1024. Same tiling. f32 atomicAdd (exactly 2 per element
// -> commutative -> deterministic).
// ============================================================
__global__ __launch_bounds__(256) void gemm2_kernel(
    const int* __restrict__ dnb,
    const int* __restrict__ dns,
    const float* __restrict__ dbias,
    float* __restrict__ out) {

    const int mtile = blockIdx.y;
    const int e  = mtile >> 4;
    const int m0 = (mtile & 15) << 7;
    const int cnt = g_count[e];
    if (m0 >= cnt) return;
    const int valid = min(128, cnt - m0);
    const int r0 = blockIdx.x << 7;
    const int off = g_off[e];

    __shared__ float As[32][128];
    __shared__ float Bs[32][128];
    __shared__ int   stok[128];
    __shared__ float scoef[128];
    __shared__ float slut[16];

    const int tid = threadIdx.x;
    if (tid < 16) slut[tid] = c_lut[tid];
    if (tid < 128) {
        int mm = (tid < valid) ? tid : 0;
        stok[tid]  = g_list[e][m0 + mm];
        scoef[tid] = g_coefs[e][m0 + mm];
    }
    __syncthreads();

    const int tx = tid & 15, ty = tid >> 4;

    const int am = tid >> 1;
    const int ak = (tid & 1) << 4;
    const int amrow = (am < valid) ? am : 0;
    const float* arowp = g_act + (size_t)(off + m0 + amrow) * D_INTER + ak;

    const int br0 = tid >> 2,         bq0 = tid & 3;
    const int br1 = (tid + 256) >> 2, bq1 = (tid + 256) & 3;
    const int4* bp0 = (const int4*)dnb + ((size_t)(e * D_HIDDEN + r0 + br0) * 128) * 4 + bq0;
    const int4* bp1 = (const int4*)dnb + ((size_t)(e * D_HIDDEN + r0 + br1) * 128) * 4 + bq1;
    const int* sp0 = dns + (size_t)(e * D_HIDDEN + r0 + br0) * 128;
    const int* sp1 = dns + (size_t)(e * D_HIDDEN + r0 + br1) * 128;

    float acc[8][8];
#pragma unroll
    for (int i = 0; i < 8; i++)
#pragma unroll
        for (int j = 0; j < 8; j++) acc[i][j] = 0.0f;

    for (int kb = 0; kb < D_INTER / 32; ++kb) {
        const float4* xp = (const float4*)(arowp + kb * 32);
        float4 a0 = xp[0], a1 = xp[1], a2 = xp[2], a3 = xp[3];
        As[ak + 0][am] = a0.x; As[ak + 1][am] = a0.y; As[ak + 2][am] = a0.z; As[ak + 3][am] = a0.w;
        As[ak + 4][am] = a1.x; As[ak + 5][am] = a1.y; As[ak + 6][am] = a1.z; As[ak + 7][am] = a1.w;
        As[ak + 8][am] = a2.x; As[ak + 9][am] = a2.y; As[ak +10][am] = a2.z; As[ak +11][am] = a2.w;
        As[ak +12][am] = a3.x; As[ak +13][am] = a3.y; As[ak +14][am] = a3.z; As[ak +15][am] = a3.w;
        {
            int4 q = bp0[kb * 4];
            float s = __int_as_float(sp0[kb] << 23);
            int vv[4] = {q.x, q.y, q.z, q.w};
#pragma unroll
            for (int ii = 0; ii < 4; ++ii) {
                int k2 = (bq0 * 4 + ii) * 2;
                Bs[k2][br0]     = slut[vv[ii] & 15] * s;
                Bs[k2 + 1][br0] = slut[(vv[ii] >> 4) & 15] * s;
            }
        }
        {
            int4 q = bp1[kb * 4];
            float s = __int_as_float(sp1[kb] << 23);
            int vv[4] = {q.x, q.y, q.z, q.w};
#pragma unroll
            for (int ii = 0; ii < 4; ++ii) {
                int k2 = (bq1 * 4 + ii) * 2;
                Bs[k2][br1]     = slut[vv[ii] & 15] * s;
                Bs[k2 + 1][br1] = slut[(vv[ii] >> 4) & 15] * s;
            }
        }
        __syncthreads();
#pragma unroll
        for (int k = 0; k < 32; k++) {
            float4 fa0 = *(const float4*)&As[k][ty * 4];
            float4 fa1 = *(const float4*)&As[k][64 + ty * 4];
            float4 fb0 = *(const float4*)&Bs[k][tx * 4];
            float4 fb1 = *(const float4*)&Bs[k][64 + tx * 4];
            float av[8] = {fa0.x, fa0.y, fa0.z, fa0.w, fa1.x, fa1.y, fa1.z, fa1.w};
            float bv[8] = {fb0.x, fb0.y, fb0.z, fb0.w, fb1.x, fb1.y, fb1.z, fb1.w};
#pragma unroll
            for (int i = 0; i < 8; i++)
#pragma unroll
                for (int j = 0; j < 8; j++) acc[i][j] += av[i] * bv[j];
        }
        __syncthreads();
    }

#pragma unroll
    for (int i = 0; i < 8; i++) {
        int m = (i < 4) ? (ty * 4 + i) : (64 + ty * 4 + (i - 4));
        if (m >= valid) continue;
        int tok = stok[m];
        float coef = scoef[m];
        float* orow = out + (size_t)tok * D_HIDDEN;
#pragma unroll
        for (int j = 0; j < 8; j++) {
            int c = (j < 4) ? (r0 + tx * 4 + j) : (r0 + 64 + tx * 4 + (j - 4));
            float v = coef * (acc[i][j] + dbias[(size_t)e * D_HIDDEN + c]);
            atomicAdd(&orow[c], v);
        }
    }
}

// ============================================================
// Launch (graph-capturable: kernels only, static worst-case grids)
// ============================================================
extern "C" void kernel_launch(void* const* d_in, const int* in_sizes, int n_in,
                              void* d_out, int out_size) {
    const float* x     = (const float*)d_in[0];
    const float* rw    = (const float*)d_in[1];
    const float* rb    = (const float*)d_in[2];
    const float* gbias = (const float*)d_in[3];
    const float* dbias = (const float*)d_in[4];
    const int*   gub   = (const int*)d_in[5];
    const int*   gus   = (const int*)d_in[6];
    const int*   dnb   = (const int*)d_in[7];
    const int*   dns   = (const int*)d_in[8];
    float* out = (float*)d_out;

    zero_kernel<<<(out_size + 255) / 256, 256>>>(out, out_size);
    router_kernel<<<NTOK / 8, 256>>>(x, rw, rb);
    compact_kernel<<<NE, 256>>>();
    offsets_kernel<<<1, 32>>>();
    gemm1_kernel<<<dim3(GU_ROWS / 128, 128), 256>>>(x, gub, gus, gbias);
    gemm2_kernel<<<dim3(D_HIDDEN / 128, 128), 256>>>(dnb, dns, dbias, out);
}

// round 4
// speedup vs baseline: 2.7167x; 2.7167x over previous
#include <cuda_runtime.h>
#include <cuda_bf16.h>
#include <math.h>
#include <stdint.h>

#define D_HIDDEN 1024
#define D_INTER  4096
#define NE       8
#define NTOK     2048
#define NPAIR    (NTOK * 2)
#define GU_ROWS  8192

// ---------------- smem layout (dynamic, bytes) ----------------
#define SM_AHI   0
#define SM_ALO   16384
#define SM_BB    32768
#define SM_TOK   49152
#define SM_COEF  49664
#define SM_TOTAL 50176

// ---------------- PTX helpers ----------------
__device__ __forceinline__ uint32_t smem_u32(const void* p) {
    uint32_t a;
    asm("{ .reg .u64 t; cvta.to.shared.u64 t, %1; cvt.u32.u64 %0, t; }" : "=r"(a) : "l"(p));
    return a;
}
#define LDSM_X4(r, addr) \
    asm volatile("ldmatrix.sync.aligned.m8n8.x4.shared.b16 {%0,%1,%2,%3}, [%4];" \
        : "=r"((r)[0]), "=r"((r)[1]), "=r"((r)[2]), "=r"((r)[3]) : "r"(addr))
#define MMA16816(c, a, b0, b1) \
    asm volatile("mma.sync.aligned.m16n8k16.row.col.f32.bf16.bf16.f32 " \
        "{%0,%1,%2,%3}, {%4,%5,%6,%7}, {%8,%9}, {%0,%1,%2,%3};" \
        : "+f"((c)[0]), "+f"((c)[1]), "+f"((c)[2]), "+f"((c)[3]) \
        : "r"((a)[0]), "r"((a)[1]), "r"((a)[2]), "r"((a)[3]), "r"(b0), "r"(b1))

// fp4 nibble pair -> packed bf16x2 bits; adjc = 0x3F00 + (scale_exp-127)<<7
__device__ __forceinline__ uint32_t dq_pair(uint32_t byte, uint32_t adjc) {
    uint32_t n0 = byte & 15u, n1 = (byte >> 4) & 15u;
    uint32_t m0 = n0 & 7u, m1 = n1 & 7u;
    uint32_t t0 = (m0 >= 2u) ? (m0 << 6) : 0u;
    uint32_t t1 = (m1 >= 2u) ? (m1 << 6) : 0u;
    uint32_t b0 = (m0 == 0u) ? 0u : (adjc + t0);
    uint32_t b1 = (m1 == 0u) ? 0u : (adjc + t1);
    b0 |= (n0 & 8u) << 12;
    b1 |= (n1 & 8u) << 12;
    return b0 | (b1 << 16);
}

// ---------------- device scratch ----------------
__device__ int   g_top_idx[NTOK][2];
__device__ float g_top_w[NTOK][2];
__device__ int   g_count[NE];
__device__ int   g_off[NE];
__device__ int   g_list[NE][NTOK];
__device__ float g_coefs[NE][NTOK];
__device__ unsigned short g_x_hi[(size_t)NTOK * D_HIDDEN];
__device__ unsigned short g_x_lo[(size_t)NTOK * D_HIDDEN];
__device__ unsigned short g_act_hi[(size_t)NPAIR * D_INTER];
__device__ unsigned short g_act_lo[(size_t)NPAIR * D_INTER];
__device__ uint4 g_gu_pack[(size_t)NE * GU_ROWS * 512 / 16];
__device__ uint4 g_dn_pack[(size_t)NE * D_HIDDEN * 2048 / 16];

// ============================================================
__global__ void zero_kernel(float* __restrict__ out, int n) {
    int i = blockIdx.x * blockDim.x + threadIdx.x;
    if (i < n) out[i] = 0.0f;
}

__global__ void prep_x_kernel(const float* __restrict__ x) {
    int row = blockIdx.x;
    int c = threadIdx.x * 4;
    float4 f = *(const float4*)(x + (size_t)row * D_HIDDEN + c);
    float v[4] = {f.x, f.y, f.z, f.w};
    unsigned short h[4], l[4];
#pragma unroll
    for (int i = 0; i < 4; i++) {
        __nv_bfloat16 hb = __float2bfloat16_rn(v[i]);
        h[i] = __bfloat16_as_ushort(hb);
        l[i] = __bfloat16_as_ushort(__float2bfloat16_rn(v[i] - __bfloat162float(hb)));
    }
    uint2 ph, pl;
    ph.x = (uint32_t)h[0] | ((uint32_t)h[1] << 16); ph.y = (uint32_t)h[2] | ((uint32_t)h[3] << 16);
    pl.x = (uint32_t)l[0] | ((uint32_t)l[1] << 16); pl.y = (uint32_t)l[2] | ((uint32_t)l[3] << 16);
    *(uint2*)(g_x_hi + (size_t)row * D_HIDDEN + c) = ph;
    *(uint2*)(g_x_lo + (size_t)row * D_HIDDEN + c) = pl;
}

__global__ void pack_kernel(const int* __restrict__ src, uint4* __restrict__ dst) {
    size_t i = (size_t)blockIdx.x * 256 + threadIdx.x;
    const int4* s = (const int4*)src + i * 4;
    int4 a = s[0], b = s[1], c = s[2], d = s[3];
    uint4 o;
    o.x = (a.x & 255) | ((a.y & 255) << 8) | ((a.z & 255) << 16) | ((a.w & 255) << 24);
    o.y = (b.x & 255) | ((b.y & 255) << 8) | ((b.z & 255) << 16) | ((b.w & 255) << 24);
    o.z = (c.x & 255) | ((c.y & 255) << 8) | ((c.z & 255) << 16) | ((c.w & 255) << 24);
    o.w = (d.x & 255) | ((d.y & 255) << 8) | ((d.z & 255) << 16) | ((d.w & 255) << 24);
    dst[i] = o;
}

// ============================================================
__global__ void router_kernel(const float* __restrict__ x,
                              const float* __restrict__ rw,
                              const float* __restrict__ rb) {
    int warp = threadIdx.x >> 5;
    int lane = threadIdx.x & 31;
    int t = blockIdx.x * 8 + warp;
    if (t >= NTOK) return;
    float acc[NE];
#pragma unroll
    for (int e = 0; e < NE; e++) acc[e] = 0.0f;
    const float* xr = x + (size_t)t * D_HIDDEN;
    for (int k = lane; k < D_HIDDEN; k += 32) {
        float xv = xr[k];
#pragma unroll
        for (int e = 0; e < NE; e++) acc[e] += xv * rw[e * D_HIDDEN + k];
    }
#pragma unroll
    for (int e = 0; e < NE; e++) {
#pragma unroll
        for (int o = 16; o > 0; o >>= 1) acc[e] += __shfl_xor_sync(0xffffffffu, acc[e], o);
    }
    if (lane == 0) {
        float v[NE];
#pragma unroll
        for (int e = 0; e < NE; e++) v[e] = acc[e] + rb[e];
        int i0 = 0;
#pragma unroll
        for (int e = 1; e < NE; e++) if (v[e] > v[i0]) i0 = e;
        int i1 = -1;
#pragma unroll
        for (int e = 0; e < NE; e++) {
            if (e == i0) continue;
            if (i1 < 0 || v[e] > v[i1]) i1 = e;
        }
        float w1 = expf(v[i1] - v[i0]);
        float inv = 1.0f / (1.0f + w1);
        g_top_idx[t][0] = i0; g_top_idx[t][1] = i1;
        g_top_w[t][0] = inv;  g_top_w[t][1] = w1 * inv;
    }
}

__global__ void compact_kernel() {
    const int e = blockIdx.x;
    const int tid = threadIdx.x;
    __shared__ int scan[256];
    __shared__ int sbase;
    if (tid == 0) sbase = 0;
    __syncthreads();
    for (int c = 0; c < NTOK; c += 256) {
        int t = c + tid;
        int i0 = g_top_idx[t][0];
        int i1 = g_top_idx[t][1];
        int flag = (i0 == e) || (i1 == e);
        float coef = (i0 == e) ? g_top_w[t][0] : g_top_w[t][1];
        scan[tid] = flag;
        __syncthreads();
#pragma unroll
        for (int off = 1; off < 256; off <<= 1) {
            int v = (tid >= off) ? scan[tid - off] : 0;
            __syncthreads();
            scan[tid] += v;
            __syncthreads();
        }
        if (flag) {
            int pos = sbase + scan[tid] - 1;
            g_list[e][pos] = t;
            g_coefs[e][pos] = coef;
        }
        __syncthreads();
        if (tid == 0) sbase += scan[255];
        __syncthreads();
    }
    if (tid == 0) g_count[e] = sbase;
}

__global__ void offsets_kernel() {
    if (threadIdx.x == 0) {
        int r = 0;
#pragma unroll
        for (int e = 0; e < NE; e++) { g_off[e] = r; r += g_count[e]; }
    }
}

// ============================================================
// GEMM1 (mma.sync bf16): act = SwiGLU(x @ Wgu^T + b), split hi/lo A
// 128x128 tile, BK=64, 8 warps (4 M x 2 N), warp tile 32x64
// ============================================================
__global__ __launch_bounds__(256, 2) void gemm1_kernel(
    const int* __restrict__ gus, const float* __restrict__ gbias) {
    const int e  = blockIdx.y >> 6;
    const int r0 = (blockIdx.y & 63) << 7;
    const int m0 = blockIdx.x << 7;
    const int cnt = g_count[e];
    if (m0 >= cnt) return;
    const int valid = min(128, cnt - m0);
    const int off = g_off[e];
    extern __shared__ char smem[];
    const uint32_t sb = smem_u32(smem);
    const int tid = threadIdx.x, wid = tid >> 5, lane = tid & 31;
    const int wm = wid & 3, wn = wid >> 2;

    int* stok = (int*)(smem + SM_TOK);
    if (tid < 128) stok[tid] = g_list[e][m0 + (tid < valid ? tid : 0)];
    __syncthreads();

    // fill mapping
    const int arow = tid >> 1;
    const int kh = (tid & 1) << 5;           // 0 or 32 elems
    const unsigned short* xh = g_x_hi + (size_t)stok[arow] * D_HIDDEN + kh;
    const unsigned short* xl = g_x_lo + (size_t)stok[arow] * D_HIDDEN + kh;
    const uint4* bw = g_gu_pack + (size_t)(e * GU_ROWS + r0 + arow) * 32;
    const int*  sc = gus + (size_t)(e * GU_ROWS + r0 + arow) * 32;
    const uint32_t fbase = (uint32_t)arow << 7;
    const uint32_t frx = ((uint32_t)arow & 7u) << 4;

    // ldmatrix address precompute
    uint32_t aAddr[2], arx[2];
#pragma unroll
    for (int mf = 0; mf < 2; mf++) {
        int r = wm * 32 + mf * 16 + (lane & 15);
        aAddr[mf] = sb + ((uint32_t)r << 7);
        arx[mf] = ((uint32_t)r & 7u) << 4;
    }
    const uint32_t a_cb = (uint32_t)(lane >> 4) << 4;
    uint32_t bAddr[4], brxv[4];
#pragma unroll
    for (int g = 0; g < 4; g++) {
        int r = wn * 64 + g * 16 + ((lane >> 4) << 3) + (lane & 7);
        bAddr[g] = sb + SM_BB + ((uint32_t)r << 7);
        brxv[g] = ((uint32_t)r & 7u) << 4;
    }
    const uint32_t b_cb = ((uint32_t)(lane >> 3) & 1u) << 4;

    float acc[2][8][4];
#pragma unroll
    for (int mf = 0; mf < 2; mf++)
#pragma unroll
        for (int nf = 0; nf < 8; nf++)
#pragma unroll
            for (int j = 0; j < 4; j++) acc[mf][nf][j] = 0.0f;

    for (int kb = 0; kb < D_HIDDEN / 64; kb++) {
        const uint4* ph = (const uint4*)(xh + kb * 64);
        const uint4* pl = (const uint4*)(xl + kb * 64);
#pragma unroll
        for (int j = 0; j < 4; j++) {
            uint32_t o = fbase + ((((uint32_t)(kh + j * 8)) << 1) ^ frx);
            *(uint4*)(smem + SM_AHI + o) = ph[j];
            *(uint4*)(smem + SM_ALO + o) = pl[j];
        }
        {
            int bi = kb * 2 + (tid & 1);
            uint4 u = bw[bi];
            uint32_t adjc = 0x3F00u + (uint32_t)((sc[bi] - 127) << 7);
            uint32_t w4[4] = {u.x, u.y, u.z, u.w};
#pragma unroll
            for (int q = 0; q < 4; q++) {
                uint32_t ww = w4[q];
                uint4 r;
                r.x = dq_pair(ww & 255u, adjc);
                r.y = dq_pair((ww >> 8) & 255u, adjc);
                r.z = dq_pair((ww >> 16) & 255u, adjc);
                r.w = dq_pair(ww >> 24, adjc);
                *(uint4*)(smem + SM_BB + fbase + ((((uint32_t)(kh + q * 8)) << 1) ^ frx)) = r;
            }
        }
        __syncthreads();
#pragma unroll
        for (int ks = 0; ks < 4; ks++) {
            uint32_t acol = (uint32_t)ks * 32 + a_cb;
            uint32_t bcol = (uint32_t)ks * 32 + b_cb;
            uint32_t Ah[2][4], Al[2][4], Bf[4][4];
#pragma unroll
            for (int mf = 0; mf < 2; mf++) {
                LDSM_X4(Ah[mf], aAddr[mf] + SM_AHI + (acol ^ arx[mf]));
                LDSM_X4(Al[mf], aAddr[mf] + SM_ALO + (acol ^ arx[mf]));
            }
#pragma unroll
            for (int g = 0; g < 4; g++) LDSM_X4(Bf[g], bAddr[g] + (bcol ^ brxv[g]));
#pragma unroll
            for (int mf = 0; mf < 2; mf++)
#pragma unroll
                for (int nf = 0; nf < 8; nf++) {
                    uint32_t bb0 = Bf[nf >> 1][(nf & 1) * 2];
                    uint32_t bb1 = Bf[nf >> 1][(nf & 1) * 2 + 1];
                    MMA16816(acc[mf][nf], Ah[mf], bb0, bb1);
                    MMA16816(acc[mf][nf], Al[mf], bb0, bb1);
                }
        }
        __syncthreads();
    }

    // ---- epilogue: bias + SwiGLU -> stage smem -> coalesced act planes ----
    const float* gb = gbias + (size_t)e * GU_ROWS;
    unsigned short* stage_hi = (unsigned short*)smem;
    unsigned short* stage_lo = (unsigned short*)(smem + 18432);
#pragma unroll
    for (int mf = 0; mf < 2; mf++)
#pragma unroll
        for (int nf = 0; nf < 8; nf++) {
            int gucol = r0 + wn * 64 + nf * 8 + (lane & 3) * 2;
            float bg = gb[gucol], bu = gb[gucol + 1];
            int cl = wn * 32 + nf * 4 + (lane & 3);
#pragma unroll
            for (int rr = 0; rr < 2; rr++) {
                int r = wm * 32 + mf * 16 + (lane >> 2) + rr * 8;
                float gate = acc[mf][nf][rr * 2 + 0] + bg;
                float up   = acc[mf][nf][rr * 2 + 1] + bu;
                gate = fminf(gate, 7.0f);
                up = fminf(fmaxf(up, -7.0f), 7.0f);
                float sg = 1.0f / (1.0f + expf(-1.702f * gate));
                float a = (up + 1.0f) * (gate * sg);
                __nv_bfloat16 hb = __float2bfloat16_rn(a);
                stage_hi[r * 72 + cl] = __bfloat16_as_ushort(hb);
                stage_lo[r * 72 + cl] =
                    __bfloat16_as_ushort(__float2bfloat16_rn(a - __bfloat162float(hb)));
            }
        }
    __syncthreads();
    {
        int row = tid >> 1;
        if (row < valid) {
            size_t gbase = (size_t)(off + m0 + row) * D_INTER + (r0 >> 1) + (tid & 1) * 32;
            uint4* dh = (uint4*)(g_act_hi + gbase);
            uint4* dl = (uint4*)(g_act_lo + gbase);
            const uint4* shp = (const uint4*)(stage_hi + row * 72 + (tid & 1) * 32);
            const uint4* slp = (const uint4*)(stage_lo + row * 72 + (tid & 1) * 32);
#pragma unroll
            for (int i = 0; i < 4; i++) { dh[i] = shp[i]; dl[i] = slp[i]; }
        }
    }
}

// ============================================================
// GEMM2 (mma.sync bf16): out += coef * (act @ Wd^T + down_bias)
// ============================================================
__global__ __launch_bounds__(256, 2) void gemm2_kernel(
    const int* __restrict__ dns, const float* __restrict__ dbias,
    float* __restrict__ out) {
    const int e  = blockIdx.y >> 3;
    const int r0 = (blockIdx.y & 7) << 7;
    const int m0 = blockIdx.x << 7;
    const int cnt = g_count[e];
    if (m0 >= cnt) return;
    const int valid = min(128, cnt - m0);
    const int off = g_off[e];
    extern __shared__ char smem[];
    const uint32_t sb = smem_u32(smem);
    const int tid = threadIdx.x, wid = tid >> 5, lane = tid & 31;
    const int wm = wid & 3, wn = wid >> 2;

    int* stok = (int*)(smem + SM_TOK);
    float* scoef = (float*)(smem + SM_COEF);
    if (tid < 128) {
        int mm = (tid < valid) ? tid : 0;
        stok[tid] = g_list[e][m0 + mm];
        scoef[tid] = g_coefs[e][m0 + mm];
    }
    __syncthreads();

    const int arow = tid >> 1;
    const int kh = (tid & 1) << 5;
    const int pr = off + m0 + ((arow < valid) ? arow : 0);
    const unsigned short* ah = g_act_hi + (size_t)pr * D_INTER + kh;
    const unsigned short* al = g_act_lo + (size_t)pr * D_INTER + kh;
    const uint4* bw = g_dn_pack + (size_t)(e * D_HIDDEN + r0 + arow) * 128;
    const int*  sc = dns + (size_t)(e * D_HIDDEN + r0 + arow) * 128;
    const uint32_t fbase = (uint32_t)arow << 7;
    const uint32_t frx = ((uint32_t)arow & 7u) << 4;

    uint32_t aAddr[2], arx[2];
#pragma unroll
    for (int mf = 0; mf < 2; mf++) {
        int r = wm * 32 + mf * 16 + (lane & 15);
        aAddr[mf] = sb + ((uint32_t)r << 7);
        arx[mf] = ((uint32_t)r & 7u) << 4;
    }
    const uint32_t a_cb = (uint32_t)(lane >> 4) << 4;
    uint32_t bAddr[4], brxv[4];
#pragma unroll
    for (int g = 0; g < 4; g++) {
        int r = wn * 64 + g * 16 + ((lane >> 4) << 3) + (lane & 7);
        bAddr[g] = sb + SM_BB + ((uint32_t)r << 7);
        brxv[g] = ((uint32_t)r & 7u) << 4;
    }
    const uint32_t b_cb = ((uint32_t)(lane >> 3) & 1u) << 4;

    float acc[2][8][4];
#pragma unroll
    for (int mf = 0; mf < 2; mf++)
#pragma unroll
        for (int nf = 0; nf < 8; nf++)
#pragma unroll
            for (int j = 0; j < 4; j++) acc[mf][nf][j] = 0.0f;

    for (int kb = 0; kb < D_INTER / 64; kb++) {
        const uint4* ph = (const uint4*)(ah + kb * 64);
        const uint4* pl = (const uint4*)(al + kb * 64);
#pragma unroll
        for (int j = 0; j < 4; j++) {
            uint32_t o = fbase + ((((uint32_t)(kh + j * 8)) << 1) ^ frx);
            *(uint4*)(smem + SM_AHI + o) = ph[j];
            *(uint4*)(smem + SM_ALO + o) = pl[j];
        }
        {
            int bi = kb * 2 + (tid & 1);
            uint4 u = bw[bi];
            uint32_t adjc = 0x3F00u + (uint32_t)((sc[bi] - 127) << 7);
            uint32_t w4[4] = {u.x, u.y, u.z, u.w};
#pragma unroll
            for (int q = 0; q < 4; q++) {
                uint32_t ww = w4[q];
                uint4 r;
                r.x = dq_pair(ww & 255u, adjc);
                r.y = dq_pair((ww >> 8) & 255u, adjc);
                r.z = dq_pair((ww >> 16) & 255u, adjc);
                r.w = dq_pair(ww >> 24, adjc);
                *(uint4*)(smem + SM_BB + fbase + ((((uint32_t)(kh + q * 8)) << 1) ^ frx)) = r;
            }
        }
        __syncthreads();
#pragma unroll
        for (int ks = 0; ks < 4; ks++) {
            uint32_t acol = (uint32_t)ks * 32 + a_cb;
            uint32_t bcol = (uint32_t)ks * 32 + b_cb;
            uint32_t Ah[2][4], Al[2][4], Bf[4][4];
#pragma unroll
            for (int mf = 0; mf < 2; mf++) {
                LDSM_X4(Ah[mf], aAddr[mf] + SM_AHI + (acol ^ arx[mf]));
                LDSM_X4(Al[mf], aAddr[mf] + SM_ALO + (acol ^ arx[mf]));
            }
#pragma unroll
            for (int g = 0; g < 4; g++) LDSM_X4(Bf[g], bAddr[g] + (bcol ^ brxv[g]));
#pragma unroll
            for (int mf = 0; mf < 2; mf++)
#pragma unroll
                for (int nf = 0; nf < 8; nf++) {
                    uint32_t bb0 = Bf[nf >> 1][(nf & 1) * 2];
                    uint32_t bb1 = Bf[nf >> 1][(nf & 1) * 2 + 1];
                    MMA16816(acc[mf][nf], Ah[mf], bb0, bb1);
                    MMA16816(acc[mf][nf], Al[mf], bb0, bb1);
                }
        }
        __syncthreads();
    }

    // ---- epilogue: out[tok] += coef * (acc + dbias), atomic (2 commuting adds) ----
    const float* db = dbias + (size_t)e * D_HIDDEN;
#pragma unroll
    for (int mf = 0; mf < 2; mf++)
#pragma unroll
        for (int nf = 0; nf < 8; nf++) {
            int gcol = r0 + wn * 64 + nf * 8 + (lane & 3) * 2;
            float b0 = db[gcol], b1 = db[gcol + 1];
#pragma unroll
            for (int rr = 0; rr < 2; rr++) {
                int m = wm * 32 + mf * 16 + (lane >> 2) + rr * 8;
                if (m < valid) {
                    float coef = scoef[m];
                    float* orow = out + (size_t)stok[m] * D_HIDDEN;
                    atomicAdd(orow + gcol,     coef * (acc[mf][nf][rr * 2 + 0] + b0));
                    atomicAdd(orow + gcol + 1, coef * (acc[mf][nf][rr * 2 + 1] + b1));
                }
            }
        }
}

// ============================================================
extern "C" void kernel_launch(void* const* d_in, const int* in_sizes, int n_in,
                              void* d_out, int out_size) {
    const float* x     = (const float*)d_in[0];
    const float* rw    = (const float*)d_in[1];
    const float* rb    = (const float*)d_in[2];
    const float* gbias = (const float*)d_in[3];
    const float* dbias = (const float*)d_in[4];
    const int*   gub   = (const int*)d_in[5];
    const int*   gus   = (const int*)d_in[6];
    const int*   dnb   = (const int*)d_in[7];
    const int*   dns   = (const int*)d_in[8];
    float* out = (float*)d_out;

    cudaFuncSetAttribute(gemm1_kernel, cudaFuncAttributeMaxDynamicSharedMemorySize, SM_TOTAL);
    cudaFuncSetAttribute(gemm2_kernel, cudaFuncAttributeMaxDynamicSharedMemorySize, SM_TOTAL);

    uint4* gu_pack; cudaGetSymbolAddress((void**)&gu_pack, g_gu_pack);
    uint4* dn_pack; cudaGetSymbolAddress((void**)&dn_pack, g_dn_pack);

    zero_kernel<<<(out_size + 255) / 256, 256>>>(out, out_size);
    prep_x_kernel<<<NTOK, 256>>>(x);
    pack_kernel<<<8192, 256>>>(gub, gu_pack);
    pack_kernel<<<4096, 256>>>(dnb, dn_pack);
    router_kernel<<<NTOK / 8, 256>>>(x, rw, rb);
    compact_kernel<<<NE, 256>>>();
    offsets_kernel<<<1, 32>>>();
    gemm1_kernel<<<dim3(16, NE * 64), 256, SM_TOTAL>>>(gus, gbias);
    gemm2_kernel<<<dim3(16, NE * 8), 256, SM_TOTAL>>>(dns, dbias, out);
}

// round 5
// speedup vs baseline: 2.7361x; 1.0071x over previous
#include <cuda_runtime.h>
#include <cuda_bf16.h>
#include <math.h>
#include <stdint.h>

#define D_HIDDEN 1024
#define D_INTER  4096
#define NE       8
#define NTOK     2048
#define NPAIR    (NTOK * 2)
#define GU_ROWS  8192

// ---------------- smem layout (dynamic, bytes) ----------------
// per-buffer: AHI 0..16K, ALO 16K..32K, B 32K..48K ; two buffers
#define SM_AHI   0
#define SM_ALO   16384
#define SM_BB    32768
#define SM_BUF   49152
#define SM_TOK   98304
#define SM_COEF  98816
#define SM_TOTAL 99328

// ---------------- PTX helpers ----------------
__device__ __forceinline__ uint32_t smem_u32(const void* p) {
    uint32_t a;
    asm("{ .reg .u64 t; cvta.to.shared.u64 t, %1; cvt.u32.u64 %0, t; }" : "=r"(a) : "l"(p));
    return a;
}
#define LDSM_X4(r, addr) \
    asm volatile("ldmatrix.sync.aligned.m8n8.x4.shared.b16 {%0,%1,%2,%3}, [%4];" \
        : "=r"((r)[0]), "=r"((r)[1]), "=r"((r)[2]), "=r"((r)[3]) : "r"(addr))
#define MMA16816(c, a, b0, b1) \
    asm volatile("mma.sync.aligned.m16n8k16.row.col.f32.bf16.bf16.f32 " \
        "{%0,%1,%2,%3}, {%4,%5,%6,%7}, {%8,%9}, {%0,%1,%2,%3};" \
        : "+f"((c)[0]), "+f"((c)[1]), "+f"((c)[2]), "+f"((c)[3]) \
        : "r"((a)[0]), "r"((a)[1]), "r"((a)[2]), "r"((a)[3]), "r"(b0), "r"(b1))
#define CP_A16(dst, src) \
    asm volatile("cp.async.cg.shared.global [%0], [%1], 16;" :: "r"(dst), "l"(src))
#define CP_COMMIT() asm volatile("cp.async.commit_group;" ::: "memory")
#define CP_WAIT0()  asm volatile("cp.async.wait_group 0;" ::: "memory")

// fp4 nibble pair -> packed bf16x2 bits; adjc = 0x3F00 + (scale_exp-127)<<7
__device__ __forceinline__ uint32_t dq_pair(uint32_t byte, uint32_t adjc) {
    uint32_t n0 = byte & 15u, n1 = (byte >> 4) & 15u;
    uint32_t m0 = n0 & 7u, m1 = n1 & 7u;
    uint32_t t0 = (m0 >= 2u) ? (m0 << 6) : 0u;
    uint32_t t1 = (m1 >= 2u) ? (m1 << 6) : 0u;
    uint32_t b0 = (m0 == 0u) ? 0u : (adjc + t0);
    uint32_t b1 = (m1 == 0u) ? 0u : (adjc + t1);
    b0 |= (n0 & 8u) << 12;
    b1 |= (n1 & 8u) << 12;
    return b0 | (b1 << 16);
}

// ---------------- device scratch ----------------
__device__ int   g_top_idx[NTOK][2];
__device__ float g_top_w[NTOK][2];
__device__ int   g_count[NE];
__device__ int   g_off[NE];
__device__ int   g_list[NE][NTOK];
__device__ float g_coefs[NE][NTOK];
__device__ unsigned short g_x_hi[(size_t)NTOK * D_HIDDEN];
__device__ unsigned short g_x_lo[(size_t)NTOK * D_HIDDEN];
__device__ unsigned short g_act_hi[(size_t)NPAIR * D_INTER];
__device__ unsigned short g_act_lo[(size_t)NPAIR * D_INTER];
__device__ uint4 g_gu_pack[(size_t)NE * GU_ROWS * 512 / 16];
__device__ uint4 g_dn_pack[(size_t)NE * D_HIDDEN * 2048 / 16];

// ============================================================
__global__ void zero_kernel(float* __restrict__ out, int n) {
    int i = blockIdx.x * blockDim.x + threadIdx.x;
    if (i < n) out[i] = 0.0f;
}

__global__ void prep_x_kernel(const float* __restrict__ x) {
    int row = blockIdx.x;
    int c = threadIdx.x * 4;
    float4 f = *(const float4*)(x + (size_t)row * D_HIDDEN + c);
    float v[4] = {f.x, f.y, f.z, f.w};
    unsigned short h[4], l[4];
#pragma unroll
    for (int i = 0; i < 4; i++) {
        __nv_bfloat16 hb = __float2bfloat16_rn(v[i]);
        h[i] = __bfloat16_as_ushort(hb);
        l[i] = __bfloat16_as_ushort(__float2bfloat16_rn(v[i] - __bfloat162float(hb)));
    }
    uint2 ph, pl;
    ph.x = (uint32_t)h[0] | ((uint32_t)h[1] << 16); ph.y = (uint32_t)h[2] | ((uint32_t)h[3] << 16);
    pl.x = (uint32_t)l[0] | ((uint32_t)l[1] << 16); pl.y = (uint32_t)l[2] | ((uint32_t)l[3] << 16);
    *(uint2*)(g_x_hi + (size_t)row * D_HIDDEN + c) = ph;
    *(uint2*)(g_x_lo + (size_t)row * D_HIDDEN + c) = pl;
}

__global__ void pack_kernel(const int* __restrict__ src, uint4* __restrict__ dst) {
    size_t i = (size_t)blockIdx.x * 256 + threadIdx.x;
    const int4* s = (const int4*)src + i * 4;
    int4 a = s[0], b = s[1], c = s[2], d = s[3];
    uint4 o;
    o.x = (a.x & 255) | ((a.y & 255) << 8) | ((a.z & 255) << 16) | ((a.w & 255) << 24);
    o.y = (b.x & 255) | ((b.y & 255) << 8) | ((b.z & 255) << 16) | ((b.w & 255) << 24);
    o.z = (c.x & 255) | ((c.y & 255) << 8) | ((c.z & 255) << 16) | ((c.w & 255) << 24);
    o.w = (d.x & 255) | ((d.y & 255) << 8) | ((d.z & 255) << 16) | ((d.w & 255) << 24);
    dst[i] = o;
}

// ============================================================
__global__ void router_kernel(const float* __restrict__ x,
                              const float* __restrict__ rw,
                              const float* __restrict__ rb) {
    int warp = threadIdx.x >> 5;
    int lane = threadIdx.x & 31;
    int t = blockIdx.x * 8 + warp;
    if (t >= NTOK) return;
    float acc[NE];
#pragma unroll
    for (int e = 0; e < NE; e++) acc[e] = 0.0f;
    const float* xr = x + (size_t)t * D_HIDDEN;
    for (int k = lane; k < D_HIDDEN; k += 32) {
        float xv = xr[k];
#pragma unroll
        for (int e = 0; e < NE; e++) acc[e] += xv * rw[e * D_HIDDEN + k];
    }
#pragma unroll
    for (int e = 0; e < NE; e++) {
#pragma unroll
        for (int o = 16; o > 0; o >>= 1) acc[e] += __shfl_xor_sync(0xffffffffu, acc[e], o);
    }
    if (lane == 0) {
        float v[NE];
#pragma unroll
        for (int e = 0; e < NE; e++) v[e] = acc[e] + rb[e];
        int i0 = 0;
#pragma unroll
        for (int e = 1; e < NE; e++) if (v[e] > v[i0]) i0 = e;
        int i1 = -1;
#pragma unroll
        for (int e = 0; e < NE; e++) {
            if (e == i0) continue;
            if (i1 < 0 || v[e] > v[i1]) i1 = e;
        }
        float w1 = expf(v[i1] - v[i0]);
        float inv = 1.0f / (1.0f + w1);
        g_top_idx[t][0] = i0; g_top_idx[t][1] = i1;
        g_top_w[t][0] = inv;  g_top_w[t][1] = w1 * inv;
    }
}

__global__ void compact_kernel() {
    const int e = blockIdx.x;
    const int tid = threadIdx.x;
    __shared__ int scan[256];
    __shared__ int sbase;
    if (tid == 0) sbase = 0;
    __syncthreads();
    for (int c = 0; c < NTOK; c += 256) {
        int t = c + tid;
        int i0 = g_top_idx[t][0];
        int i1 = g_top_idx[t][1];
        int flag = (i0 == e) || (i1 == e);
        float coef = (i0 == e) ? g_top_w[t][0] : g_top_w[t][1];
        scan[tid] = flag;
        __syncthreads();
#pragma unroll
        for (int off = 1; off < 256; off <<= 1) {
            int v = (tid >= off) ? scan[tid - off] : 0;
            __syncthreads();
            scan[tid] += v;
            __syncthreads();
        }
        if (flag) {
            int pos = sbase + scan[tid] - 1;
            g_list[e][pos] = t;
            g_coefs[e][pos] = coef;
        }
        __syncthreads();
        if (tid == 0) sbase += scan[255];
        __syncthreads();
    }
    if (tid == 0) g_count[e] = sbase;
}

__global__ void offsets_kernel() {
    if (threadIdx.x == 0) {
        int r = 0;
#pragma unroll
        for (int e = 0; e < NE; e++) { g_off[e] = r; r += g_count[e]; }
    }
}

// ============================================================
// GEMM1 (mma.sync bf16, cp.async double-buffered pipeline)
// 128x128 tile, BK=64, 8 warps (4 M x 2 N), warp tile 32x64
// ============================================================
__global__ __launch_bounds__(256, 2) void gemm1_kernel(
    const int* __restrict__ gus, const float* __restrict__ gbias) {
    const int e  = blockIdx.y >> 6;
    const int r0 = (blockIdx.y & 63) << 7;
    const int m0 = blockIdx.x << 7;
    const int cnt = g_count[e];
    if (m0 >= cnt) return;
    const int valid = min(128, cnt - m0);
    const int off = g_off[e];
    extern __shared__ char smem[];
    const uint32_t sb = smem_u32(smem);
    const int tid = threadIdx.x, wid = tid >> 5, lane = tid & 31;
    const int wm = wid & 3, wn = wid >> 2;

    int* stok = (int*)(smem + SM_TOK);
    if (tid < 128) stok[tid] = g_list[e][m0 + (tid < valid ? tid : 0)];
    __syncthreads();

    // fill mapping
    const int arow = tid >> 1;
    const int kh = (tid & 1) << 5;           // 0 or 32 elems
    const unsigned short* xh = g_x_hi + (size_t)stok[arow] * D_HIDDEN + kh;
    const unsigned short* xl = g_x_lo + (size_t)stok[arow] * D_HIDDEN + kh;
    const uint4* bw = g_gu_pack + (size_t)(e * GU_ROWS + r0 + arow) * 32;
    const int*  sc = gus + (size_t)(e * GU_ROWS + r0 + arow) * 32;
    const uint32_t fbase = (uint32_t)arow << 7;
    const uint32_t frx = ((uint32_t)arow & 7u) << 4;
    uint32_t fo[4];
#pragma unroll
    for (int j = 0; j < 4; j++)
        fo[j] = fbase + ((((uint32_t)(kh + j * 8)) << 1) ^ frx);

    // ldmatrix address precompute
    uint32_t aAddr[2], arx[2];
#pragma unroll
    for (int mf = 0; mf < 2; mf++) {
        int r = wm * 32 + mf * 16 + (lane & 15);
        aAddr[mf] = sb + ((uint32_t)r << 7);
        arx[mf] = ((uint32_t)r & 7u) << 4;
    }
    const uint32_t a_cb = (uint32_t)(lane >> 4) << 4;
    uint32_t bAddr[4], brxv[4];
#pragma unroll
    for (int g = 0; g < 4; g++) {
        int r = wn * 64 + g * 16 + ((lane >> 4) << 3) + (lane & 7);
        bAddr[g] = sb + SM_BB + ((uint32_t)r << 7);
        brxv[g] = ((uint32_t)r & 7u) << 4;
    }
    const uint32_t b_cb = ((uint32_t)(lane >> 3) & 1u) << 4;

    float acc[2][8][4];
#pragma unroll
    for (int mf = 0; mf < 2; mf++)
#pragma unroll
        for (int nf = 0; nf < 8; nf++)
#pragma unroll
            for (int j = 0; j < 4; j++) acc[mf][nf][j] = 0.0f;

    // ---- prologue: async A(0), B(0) regs ----
#pragma unroll
    for (int j = 0; j < 4; j++) {
        CP_A16(sb + SM_AHI + fo[j], xh + j * 8);
        CP_A16(sb + SM_ALO + fo[j], xl + j * 8);
    }
    CP_COMMIT();
    uint4 ub = bw[tid & 1];
    uint32_t adj = 0x3F00u + (uint32_t)((sc[tid & 1] - 127) << 7);

    const int NKB = D_HIDDEN / 64;
    for (int kb = 0; kb < NKB; kb++) {
        const uint32_t bo = (uint32_t)(kb & 1) * SM_BUF;
        // dequant-store B(kb) from prefetched regs
        {
            uint32_t w4[4] = {ub.x, ub.y, ub.z, ub.w};
#pragma unroll
            for (int q = 0; q < 4; q++) {
                uint32_t ww = w4[q];
                uint4 r;
                r.x = dq_pair(ww & 255u, adj);
                r.y = dq_pair((ww >> 8) & 255u, adj);
                r.z = dq_pair((ww >> 16) & 255u, adj);
                r.w = dq_pair(ww >> 24, adj);
                *(uint4*)(smem + bo + SM_BB + fo[q]) = r;
            }
        }
        CP_WAIT0();
        __syncthreads();
        if (kb + 1 < NKB) {
            const uint32_t bo2 = (uint32_t)((kb + 1) & 1) * SM_BUF;
#pragma unroll
            for (int j = 0; j < 4; j++) {
                CP_A16(sb + bo2 + SM_AHI + fo[j], xh + (kb + 1) * 64 + j * 8);
                CP_A16(sb + bo2 + SM_ALO + fo[j], xl + (kb + 1) * 64 + j * 8);
            }
            CP_COMMIT();
            int bin = (kb + 1) * 2 + (tid & 1);
            ub = bw[bin];
            adj = 0x3F00u + (uint32_t)((sc[bin] - 127) << 7);
        }
#pragma unroll
        for (int ks = 0; ks < 4; ks++) {
            uint32_t acol = (uint32_t)ks * 32 + a_cb;
            uint32_t bcol = (uint32_t)ks * 32 + b_cb;
            uint32_t Ah[2][4], Al[2][4], Bf[4][4];
#pragma unroll
            for (int mf = 0; mf < 2; mf++) {
                LDSM_X4(Ah[mf], aAddr[mf] + bo + SM_AHI + (acol ^ arx[mf]));
                LDSM_X4(Al[mf], aAddr[mf] + bo + SM_ALO + (acol ^ arx[mf]));
            }
#pragma unroll
            for (int g = 0; g < 4; g++) LDSM_X4(Bf[g], bAddr[g] + bo + (bcol ^ brxv[g]));
#pragma unroll
            for (int mf = 0; mf < 2; mf++)
#pragma unroll
                for (int nf = 0; nf < 8; nf++) {
                    uint32_t bb0 = Bf[nf >> 1][(nf & 1) * 2];
                    uint32_t bb1 = Bf[nf >> 1][(nf & 1) * 2 + 1];
                    MMA16816(acc[mf][nf], Ah[mf], bb0, bb1);
                    MMA16816(acc[mf][nf], Al[mf], bb0, bb1);
                }
        }
    }
    __syncthreads();

    // ---- epilogue: bias + SwiGLU -> stage smem -> coalesced act planes ----
    const float* gb = gbias + (size_t)e * GU_ROWS;
    unsigned short* stage_hi = (unsigned short*)smem;
    unsigned short* stage_lo = (unsigned short*)(smem + 18432);
#pragma unroll
    for (int mf = 0; mf < 2; mf++)
#pragma unroll
        for (int nf = 0; nf < 8; nf++) {
            int gucol = r0 + wn * 64 + nf * 8 + (lane & 3) * 2;
            float bg = gb[gucol], bu = gb[gucol + 1];
            int cl = wn * 32 + nf * 4 + (lane & 3);
#pragma unroll
            for (int rr = 0; rr < 2; rr++) {
                int r = wm * 32 + mf * 16 + (lane >> 2) + rr * 8;
                float gate = acc[mf][nf][rr * 2 + 0] + bg;
                float up   = acc[mf][nf][rr * 2 + 1] + bu;
                gate = fminf(gate, 7.0f);
                up = fminf(fmaxf(up, -7.0f), 7.0f);
                float sg = 1.0f / (1.0f + __expf(-1.702f * gate));
                float a = (up + 1.0f) * (gate * sg);
                __nv_bfloat16 hb = __float2bfloat16_rn(a);
                stage_hi[r * 72 + cl] = __bfloat16_as_ushort(hb);
                stage_lo[r * 72 + cl] =
                    __bfloat16_as_ushort(__float2bfloat16_rn(a - __bfloat162float(hb)));
            }
        }
    __syncthreads();
    {
        int row = tid >> 1;
        if (row < valid) {
            size_t gbase = (size_t)(off + m0 + row) * D_INTER + (r0 >> 1) + (tid & 1) * 32;
            uint4* dh = (uint4*)(g_act_hi + gbase);
            uint4* dl = (uint4*)(g_act_lo + gbase);
            const uint4* shp = (const uint4*)(stage_hi + row * 72 + (tid & 1) * 32);
            const uint4* slp = (const uint4*)(stage_lo + row * 72 + (tid & 1) * 32);
#pragma unroll
            for (int i = 0; i < 4; i++) { dh[i] = shp[i]; dl[i] = slp[i]; }
        }
    }
}

// ============================================================
// GEMM2 (mma.sync bf16, cp.async double-buffered pipeline)
// ============================================================
__global__ __launch_bounds__(256, 2) void gemm2_kernel(
    const int* __restrict__ dns, const float* __restrict__ dbias,
    float* __restrict__ out) {
    const int e  = blockIdx.y >> 3;
    const int r0 = (blockIdx.y & 7) << 7;
    const int m0 = blockIdx.x << 7;
    const int cnt = g_count[e];
    if (m0 >= cnt) return;
    const int valid = min(128, cnt - m0);
    const int off = g_off[e];
    extern __shared__ char smem[];
    const uint32_t sb = smem_u32(smem);
    const int tid = threadIdx.x, wid = tid >> 5, lane = tid & 31;
    const int wm = wid & 3, wn = wid >> 2;

    int* stok = (int*)(smem + SM_TOK);
    float* scoef = (float*)(smem + SM_COEF);
    if (tid < 128) {
        int mm = (tid < valid) ? tid : 0;
        stok[tid] = g_list[e][m0 + mm];
        scoef[tid] = g_coefs[e][m0 + mm];
    }
    __syncthreads();

    const int arow = tid >> 1;
    const int kh = (tid & 1) << 5;
    const int pr = off + m0 + ((arow < valid) ? arow : 0);
    const unsigned short* ah = g_act_hi + (size_t)pr * D_INTER + kh;
    const unsigned short* al = g_act_lo + (size_t)pr * D_INTER + kh;
    const uint4* bw = g_dn_pack + (size_t)(e * D_HIDDEN + r0 + arow) * 128;
    const int*  sc = dns + (size_t)(e * D_HIDDEN + r0 + arow) * 128;
    const uint32_t fbase = (uint32_t)arow << 7;
    const uint32_t frx = ((uint32_t)arow & 7u) << 4;
    uint32_t fo[4];
#pragma unroll
    for (int j = 0; j < 4; j++)
        fo[j] = fbase + ((((uint32_t)(kh + j * 8)) << 1) ^ frx);

    uint32_t aAddr[2], arx[2];
#pragma unroll
    for (int mf = 0; mf < 2; mf++) {
        int r = wm * 32 + mf * 16 + (lane & 15);
        aAddr[mf] = sb + ((uint32_t)r << 7);
        arx[mf] = ((uint32_t)r & 7u) << 4;
    }
    const uint32_t a_cb = (uint32_t)(lane >> 4) << 4;
    uint32_t bAddr[4], brxv[4];
#pragma unroll
    for (int g = 0; g < 4; g++) {
        int r = wn * 64 + g * 16 + ((lane >> 4) << 3) + (lane & 7);
        bAddr[g] = sb + SM_BB + ((uint32_t)r << 7);
        brxv[g] = ((uint32_t)r & 7u) << 4;
    }
    const uint32_t b_cb = ((uint32_t)(lane >> 3) & 1u) << 4;

    float acc[2][8][4];
#pragma unroll
    for (int mf = 0; mf < 2; mf++)
#pragma unroll
        for (int nf = 0; nf < 8; nf++)
#pragma unroll
            for (int j = 0; j < 4; j++) acc[mf][nf][j] = 0.0f;

    // ---- prologue ----
#pragma unroll
    for (int j = 0; j < 4; j++) {
        CP_A16(sb + SM_AHI + fo[j], ah + j * 8);
        CP_A16(sb + SM_ALO + fo[j], al + j * 8);
    }
    CP_COMMIT();
    uint4 ub = bw[tid & 1];
    uint32_t adj = 0x3F00u + (uint32_t)((sc[tid & 1] - 127) << 7);

    const int NKB = D_INTER / 64;
    for (int kb = 0; kb < NKB; kb++) {
        const uint32_t bo = (uint32_t)(kb & 1) * SM_BUF;
        {
            uint32_t w4[4] = {ub.x, ub.y, ub.z, ub.w};
#pragma unroll
            for (int q = 0; q < 4; q++) {
                uint32_t ww = w4[q];
                uint4 r;
                r.x = dq_pair(ww & 255u, adj);
                r.y = dq_pair((ww >> 8) & 255u, adj);
                r.z = dq_pair((ww >> 16) & 255u, adj);
                r.w = dq_pair(ww >> 24, adj);
                *(uint4*)(smem + bo + SM_BB + fo[q]) = r;
            }
        }
        CP_WAIT0();
        __syncthreads();
        if (kb + 1 < NKB) {
            const uint32_t bo2 = (uint32_t)((kb + 1) & 1) * SM_BUF;
#pragma unroll
            for (int j = 0; j < 4; j++) {
                CP_A16(sb + bo2 + SM_AHI + fo[j], ah + (kb + 1) * 64 + j * 8);
                CP_A16(sb + bo2 + SM_ALO + fo[j], al + (kb + 1) * 64 + j * 8);
            }
            CP_COMMIT();
            int bin = (kb + 1) * 2 + (tid & 1);
            ub = bw[bin];
            adj = 0x3F00u + (uint32_t)((sc[bin] - 127) << 7);
        }
#pragma unroll
        for (int ks = 0; ks < 4; ks++) {
            uint32_t acol = (uint32_t)ks * 32 + a_cb;
            uint32_t bcol = (uint32_t)ks * 32 + b_cb;
            uint32_t Ah[2][4], Al[2][4], Bf[4][4];
#pragma unroll
            for (int mf = 0; mf < 2; mf++) {
                LDSM_X4(Ah[mf], aAddr[mf] + bo + SM_AHI + (acol ^ arx[mf]));
                LDSM_X4(Al[mf], aAddr[mf] + bo + SM_ALO + (acol ^ arx[mf]));
            }
#pragma unroll
            for (int g = 0; g < 4; g++) LDSM_X4(Bf[g], bAddr[g] + bo + (bcol ^ brxv[g]));
#pragma unroll
            for (int mf = 0; mf < 2; mf++)
#pragma unroll
                for (int nf = 0; nf < 8; nf++) {
                    uint32_t bb0 = Bf[nf >> 1][(nf & 1) * 2];
                    uint32_t bb1 = Bf[nf >> 1][(nf & 1) * 2 + 1];
                    MMA16816(acc[mf][nf], Ah[mf], bb0, bb1);
                    MMA16816(acc[mf][nf], Al[mf], bb0, bb1);
                }
        }
    }

    // ---- epilogue: out[tok] += coef * (acc + dbias), atomic (2 commuting adds) ----
    const float* db = dbias + (size_t)e * D_HIDDEN;
#pragma unroll
    for (int mf = 0; mf < 2; mf++)
#pragma unroll
        for (int nf = 0; nf < 8; nf++) {
            int gcol = r0 + wn * 64 + nf * 8 + (lane & 3) * 2;
            float b0 = db[gcol], b1 = db[gcol + 1];
#pragma unroll
            for (int rr = 0; rr < 2; rr++) {
                int m = wm * 32 + mf * 16 + (lane >> 2) + rr * 8;
                if (m < valid) {
                    float coef = scoef[m];
                    float* orow = out + (size_t)stok[m] * D_HIDDEN;
                    atomicAdd(orow + gcol,     coef * (acc[mf][nf][rr * 2 + 0] + b0));
                    atomicAdd(orow + gcol + 1, coef * (acc[mf][nf][rr * 2 + 1] + b1));
                }
            }
        }
}

// ============================================================
extern "C" void kernel_launch(void* const* d_in, const int* in_sizes, int n_in,
                              void* d_out, int out_size) {
    const float* x     = (const float*)d_in[0];
    const float* rw    = (const float*)d_in[1];
    const float* rb    = (const float*)d_in[2];
    const float* gbias = (const float*)d_in[3];
    const float* dbias = (const float*)d_in[4];
    const int*   gub   = (const int*)d_in[5];
    const int*   gus   = (const int*)d_in[6];
    const int*   dnb   = (const int*)d_in[7];
    const int*   dns   = (const int*)d_in[8];
    float* out = (float*)d_out;

    cudaFuncSetAttribute(gemm1_kernel, cudaFuncAttributeMaxDynamicSharedMemorySize, SM_TOTAL);
    cudaFuncSetAttribute(gemm2_kernel, cudaFuncAttributeMaxDynamicSharedMemorySize, SM_TOTAL);

    uint4* gu_pack; cudaGetSymbolAddress((void**)&gu_pack, g_gu_pack);
    uint4* dn_pack; cudaGetSymbolAddress((void**)&dn_pack, g_dn_pack);

    zero_kernel<<<(out_size + 255) / 256, 256>>>(out, out_size);
    prep_x_kernel<<<NTOK, 256>>>(x);
    pack_kernel<<<8192, 256>>>(gub, gu_pack);
    pack_kernel<<<4096, 256>>>(dnb, dn_pack);
    router_kernel<<<NTOK / 8, 256>>>(x, rw, rb);
    compact_kernel<<<NE, 256>>>();
    offsets_kernel<<<1, 32>>>();
    gemm1_kernel<<<dim3(16, NE * 64), 256, SM_TOTAL>>>(gus, gbias);
    gemm2_kernel<<<dim3(16, NE * 8), 256, SM_TOTAL>>>(dns, dbias, out);
}